// round 13
// baseline (speedup 1.0000x reference)
#include <cuda_runtime.h>

// PlasticNet: T=64 steps, B=32, I=128, H=256, clip=2.0
// out = [ ys (T*B*H) | h_f (B*H) | hebb_f (B*H*H) ]  float32
//
// Single kernel: 32 clusters of 4 CTAs (one per sample). CTA c owns
// presynaptic rows [c*64, c*64+64); thread t owns column t.
// Prologue: CTA c computes xwi = x@Wi+bi for steps [16c,16c+16) (coherent
// __ldcg cross-CTA, ordered by the one-time init cluster barrier).
// hebb in saturated space hbs=(hebb+2)/4: clip = free .sat on FFMA.
// Steady-state sync: NO cross-CTA barriers. Each thread pushes (tag=step,
// partial) as one 8B st.shared::cluster.b64 into the 3 peers' SMEM; consumers
// spin on LOCAL smem (batched loads). h triple-buffered -> only ONE
// __syncthreads per step (before the sweep).

static constexpr int kT = 64;
static constexpr int kB = 32;
static constexpr int kI = 128;
static constexpr int kH = 256;
static constexpr int kRows = 64;
static constexpr int kNCTA = kB * 4;
static constexpr int kThreads = 256;

typedef unsigned long long ull;

__device__ float g_xwi[kT * kB * kH];              // x@Wi + bi

// ---------------------------------------------------------------------------
// PTX helpers
// ---------------------------------------------------------------------------
__device__ __forceinline__ unsigned smem_u32(const void* p) {
    return (unsigned)__cvta_generic_to_shared(p);
}
__device__ __forceinline__ unsigned mapa_u32(unsigned addr, unsigned rank) {
    unsigned o;
    asm("mapa.shared::cluster.u32 %0, %1, %2;" : "=r"(o) : "r"(addr), "r"(rank));
    return o;
}
__device__ __forceinline__ void st_cluster_u64(unsigned addr, ull v) {
    asm volatile("st.shared::cluster.b64 [%0], %1;" :: "r"(addr), "l"(v) : "memory");
}
__device__ __forceinline__ ull ld_vol_smem_u64(unsigned addr) {
    ull v;
    asm volatile("ld.volatile.shared.b64 %0, [%1];" : "=l"(v) : "r"(addr));
    return v;
}
__device__ __forceinline__ void cluster_sync_all() {
    asm volatile("barrier.cluster.arrive.aligned;" ::: "memory");
    asm volatile("barrier.cluster.wait.aligned;" ::: "memory");
}

// ---- f32x2 packed math ----
__device__ __forceinline__ ull pack2(float lo, float hi) {
    ull r; asm("mov.b64 %0, {%1, %2};" : "=l"(r) : "f"(lo), "f"(hi)); return r;
}
__device__ __forceinline__ void unpack2(ull v, float& lo, float& hi) {
    asm("mov.b64 {%0, %1}, %2;" : "=f"(lo), "=f"(hi) : "l"(v));
}
__device__ __forceinline__ ull fma2(ull a, ull b, ull c) {
    ull d; asm("fma.rn.f32x2 %0, %1, %2, %3;" : "=l"(d) : "l"(a), "l"(b), "l"(c));
    return d;
}
// saturating scalar fma: clamps result to [0,1] as a free output modifier
__device__ __forceinline__ float fma_sat(float a, float b, float c) {
    float d; asm("fma.rn.sat.f32 %0, %1, %2, %3;" : "=f"(d) : "f"(a), "f"(b), "f"(c));
    return d;
}

// ---------------------------------------------------------------------------
__global__ void __launch_bounds__(kThreads, 1) __cluster_dims__(4, 1, 1)
plastic_kernel(const float* __restrict__ x,
               const float* __restrict__ Wi,
               const float* __restrict__ bi,
               const float* __restrict__ w,
               const float* __restrict__ alpha,
               const float* __restrict__ Wm,
               const float* __restrict__ bm,
               const float* __restrict__ Wf,
               const float* __restrict__ bf,
               float* __restrict__ out) {
    const int b = blockIdx.x >> 2;
    const int c = blockIdx.x & 3;      // cluster ctarank
    const int t = threadIdx.x;
    const int lane = t & 31;
    const int wid = t >> 5;
    const int i0 = c * kRows;

    __shared__ __align__(16) float hbuf[3][kH];       // h TRIPLE buffer
    __shared__ __align__(16) ull slots[2][4][kH];     // (tag,value) msgs, dbl buf
    __shared__ __align__(16) float wpart[8];          // per-warp eta partials

    // ======== prologue: xwi for steps [16c, 16c+16) of sample b ========
    {
        float* xs = reinterpret_cast<float*>(slots);  // 8KB scratch alias
        const float bi_t = __ldg(&bi[t]);
        const int s0 = c * 16;
        if (t < kI) {
#pragma unroll
            for (int s = 0; s < 16; ++s)
                xs[s * kI + t] = __ldg(&x[((s0 + s) * kB + b) * kI + t]);
        }
        __syncthreads();
        float acc[16];
#pragma unroll
        for (int s = 0; s < 16; ++s) acc[s] = bi_t;
#pragma unroll 4
        for (int ib = 0; ib < kI; ib += 4) {
            const float q0 = __ldg(&Wi[(ib + 0) * kH + t]);
            const float q1 = __ldg(&Wi[(ib + 1) * kH + t]);
            const float q2 = __ldg(&Wi[(ib + 2) * kH + t]);
            const float q3 = __ldg(&Wi[(ib + 3) * kH + t]);
#pragma unroll
            for (int s = 0; s < 16; ++s) {
                const float4 xv = *reinterpret_cast<const float4*>(&xs[s * kI + ib]);
                acc[s] = fmaf(xv.w, q3, fmaf(xv.z, q2,
                         fmaf(xv.y, q1, fmaf(xv.x, q0, acc[s]))));
            }
        }
#pragma unroll
        for (int s = 0; s < 16; ++s)
            g_xwi[((s0 + s) * kB + b) * kH + t] = acc[s];
    }
    __syncthreads();   // xs scratch reads done before slot tag init below

    // ======== register state: rows i0+2j, i0+2j+1, column t ========
    // wv2 = (w - 2a) pair, av2 = (4a) pair, hbs = (hebb+2)/4 in [0,1]
    ull wv2[32], av2[32];
    float hbL[32], hbH[32];
#pragma unroll
    for (int j = 0; j < 32; ++j) {
        const float w0 = __ldg(&w[(i0 + 2 * j) * kH + t]);
        const float w1 = __ldg(&w[(i0 + 2 * j + 1) * kH + t]);
        const float a0 = __ldg(&alpha[(i0 + 2 * j) * kH + t]);
        const float a1 = __ldg(&alpha[(i0 + 2 * j + 1) * kH + t]);
        wv2[j] = pack2(fmaf(-2.f, a0, w0), fmaf(-2.f, a1, w1));
        av2[j] = pack2(4.f * a0, 4.f * a1);
        hbL[j] = 0.5f;   // hebb = 0
        hbH[j] = 0.5f;
    }
    const float wf_t = __ldg(&Wf[t]);
    const float bf_t = __ldg(&bf[t]);
    const float wm_t = __ldg(&Wm[t]);
    const float bm0 = __ldg(&bm[0]);

    // invalid tags everywhere (0xFFFFFFFF != any step)
#pragma unroll
    for (int p = 0; p < 2; ++p)
#pragma unroll
        for (int r = 0; r < 4; ++r)
            slots[p][r][t] = 0xFFFFFFFF00000000ull;
    hbuf[2][t] = 0.f;   // h_{-1} = 0 lives in buffer 2 (prev of step 0)
    __syncthreads();
    // one-time barrier: peers' smem live, g_xwi stores visible to __ldcg
    cluster_sync_all();

    // push addresses (3 peers, both parities) + local spin addresses
    unsigned pr_addr[2][3], sl_addr[2][3];
#pragma unroll
    for (int p = 0; p < 2; ++p) {
        const unsigned lr = smem_u32(&slots[p][c][t]);
#pragma unroll
        for (int d = 1; d < 4; ++d) {
            pr_addr[p][d - 1] = mapa_u32(lr, (unsigned)((c + d) & 3));
            sl_addr[p][d - 1] = smem_u32(&slots[p][(c + d) & 3][t]);
        }
    }

    float* __restrict__ ys = out;
    float* __restrict__ hf = out + kT * kB * kH;
    float* __restrict__ hebbf = out + kT * kB * kH + kB * kH;

    // step 0: h_{-1}=0 -> rec=0 -> h = tanh(xwi[0])  (coherent load)
    float h_cur = tanhf(__ldcg(&g_xwi[b * kH + t]));

    int cur = 0, prv = 2;   // h_step buffer rotation (3 buffers)
    for (int step = 0; step < kT; ++step) {
        const int par = step & 1;
        const float* __restrict__ hp = hbuf[prv];        // h_{step-1}
        float* __restrict__ hn = hbuf[cur];              // h_step

        // prefetch next step's xwi early (coherent; hides L2 latency)
        float xw_next = 0.f;
        if (step < kT - 1)
            xw_next = __ldcg(&g_xwi[((step + 1) * kB + b) * kH + t]);

        hn[t] = h_cur;
        if (c == 0) ys[(step * kB + b) * kH + t] = h_cur;
        // eta partial: warp-level reduce of h.Wm, pre-sync
        float s = h_cur * wm_t;
#pragma unroll
        for (int off = 16; off; off >>= 1)
            s += __shfl_xor_sync(0xffffffffu, s, off);
        if (lane == 0) wpart[wid] = s;
        __syncthreads();   // the ONLY per-step CTA barrier

        // ---- eta = tanh(h . Wm + bm) ----
        const float4 wp0 = *reinterpret_cast<const float4*>(&wpart[0]);
        const float4 wp1 = *reinterpret_cast<const float4*>(&wpart[4]);
        const float eta = tanhf(((wp0.x + wp0.y) + (wp0.z + wp0.w)) +
                                ((wp1.x + wp1.y) + (wp1.z + wp1.w)) + bm0);
        const float v = fmaf(eta, wf_t, bf_t) * h_cur;    // me_t * h_t
        const float v4 = 0.25f * v;                       // exact scale

        // ---- fused sweep: hbs = sat(hbs + v4*hp), pr += hn*(w' + a'*hbs) ----
        ull prA = 0ull, prB = 0ull;
#pragma unroll
        for (int jj = 0; jj < 16; ++jj) {
            const float4 hp4 = *reinterpret_cast<const float4*>(&hp[i0 + 4 * jj]);
            const float4 hn4 = *reinterpret_cast<const float4*>(&hn[i0 + 4 * jj]);
            const int j = 2 * jj;
            hbL[j]     = fma_sat(v4, hp4.x, hbL[j]);
            hbH[j]     = fma_sat(v4, hp4.y, hbH[j]);
            hbL[j + 1] = fma_sat(v4, hp4.z, hbL[j + 1]);
            hbH[j + 1] = fma_sat(v4, hp4.w, hbH[j + 1]);
            prA = fma2(pack2(hn4.x, hn4.y),
                       fma2(av2[j], pack2(hbL[j], hbH[j]), wv2[j]), prA);
            prB = fma2(pack2(hn4.z, hn4.w),
                       fma2(av2[j + 1], pack2(hbL[j + 1], hbH[j + 1]), wv2[j + 1]), prB);
        }

        if (step < kT - 1) {
            float pa, pb, pc_, pd;
            unpack2(prA, pa, pb);
            unpack2(prB, pc_, pd);
            const float pr = (pa + pb) + (pc_ + pd);
            // push (tag=step, pr) as ONE 8B single-copy-atomic DSMEM store
            const ull msg = ((ull)(unsigned)step << 32) |
                            (ull)(unsigned)__float_as_uint(pr);
            st_cluster_u64(pr_addr[par][0], msg);
            st_cluster_u64(pr_addr[par][1], msg);
            st_cluster_u64(pr_addr[par][2], msg);
            // batched spin: 3 independent loads pipelined, re-poll on miss
            const unsigned tag = (unsigned)step;
            ull v0 = ld_vol_smem_u64(sl_addr[par][0]);
            ull v1 = ld_vol_smem_u64(sl_addr[par][1]);
            ull v2 = ld_vol_smem_u64(sl_addr[par][2]);
            while ((unsigned)(v0 >> 32) != tag) v0 = ld_vol_smem_u64(sl_addr[par][0]);
            while ((unsigned)(v1 >> 32) != tag) v1 = ld_vol_smem_u64(sl_addr[par][1]);
            while ((unsigned)(v2 >> 32) != tag) v2 = ld_vol_smem_u64(sl_addr[par][2]);
            const float q0 = __uint_as_float((unsigned)v0);
            const float q1 = __uint_as_float((unsigned)v1);
            const float q2 = __uint_as_float((unsigned)v2);
            // NO barrier here: h triple-buffering makes next step's hn write
            // safe, and slot-parity reuse is ordered via the per-step
            // __syncthreads chain (see analysis in commit message).
            h_cur = tanhf(xw_next + ((pr + q0) + (q1 + q2)));
        }

        prv = cur;
        cur = (cur == 2) ? 0 : cur + 1;
    }

    // ---- final outputs (hebb = 4*hbs - 2) ----
    if (c == 0) hf[b * kH + t] = h_cur;    // h at step T-1
#pragma unroll
    for (int j = 0; j < 32; ++j) {
        hebbf[(size_t)b * kH * kH + (i0 + 2 * j) * kH + t] =
            fmaf(4.f, hbL[j], -2.f);
        hebbf[(size_t)b * kH * kH + (i0 + 2 * j + 1) * kH + t] =
            fmaf(4.f, hbH[j], -2.f);
    }
}

// ---------------------------------------------------------------------------
extern "C" void kernel_launch(void* const* d_in, const int* in_sizes, int n_in,
                              void* d_out, int out_size) {
    const float* x     = (const float*)d_in[0];
    const float* Wi    = (const float*)d_in[1];
    const float* bi    = (const float*)d_in[2];
    const float* w     = (const float*)d_in[3];
    const float* alpha = (const float*)d_in[4];
    const float* Wm    = (const float*)d_in[5];
    const float* bm    = (const float*)d_in[6];
    const float* Wf    = (const float*)d_in[7];
    const float* bf    = (const float*)d_in[8];
    float* out = (float*)d_out;

    plastic_kernel<<<kNCTA, kThreads>>>(x, Wi, bi, w, alpha, Wm, bm, Wf, bf, out);
}

// round 14
// speedup vs baseline: 1.0541x; 1.0541x over previous
#include <cuda_runtime.h>

// PlasticNet: T=64 steps, B=32, I=128, H=256, clip=2.0
// out = [ ys (T*B*H) | h_f (B*H) | hebb_f (B*H*H) ]  float32
//
// Single kernel: 32 clusters of 4 CTAs (one per sample). CTA c owns
// presynaptic rows [c*64, c*64+64); thread t owns column t.
// Prologue: CTA c computes xwi = x@Wi+bi for steps [16c,16c+16) (coherent
// __ldcg cross-CTA, ordered by the one-time init cluster barrier).
// hebb in saturated space hbs=(hebb+2)/4: clip = free .sat on FFMA.
// Steady-state sync (R12 scheme, proven): push (tag=step, partial) as one 8B
// st.shared::cluster.b64 to 3 peers, batched local spin, then __syncthreads.
// Step loop unrolled x2 so ALL parity-dependent addresses/pointers are
// compile-time constants (no dynamic register-array indexing).

static constexpr int kT = 64;
static constexpr int kB = 32;
static constexpr int kI = 128;
static constexpr int kH = 256;
static constexpr int kRows = 64;
static constexpr int kNCTA = kB * 4;
static constexpr int kThreads = 256;

typedef unsigned long long ull;

__device__ float g_xwi[kT * kB * kH];              // x@Wi + bi

// ---------------------------------------------------------------------------
// PTX helpers
// ---------------------------------------------------------------------------
__device__ __forceinline__ unsigned smem_u32(const void* p) {
    return (unsigned)__cvta_generic_to_shared(p);
}
__device__ __forceinline__ unsigned mapa_u32(unsigned addr, unsigned rank) {
    unsigned o;
    asm("mapa.shared::cluster.u32 %0, %1, %2;" : "=r"(o) : "r"(addr), "r"(rank));
    return o;
}
__device__ __forceinline__ void st_cluster_u64(unsigned addr, ull v) {
    asm volatile("st.shared::cluster.b64 [%0], %1;" :: "r"(addr), "l"(v) : "memory");
}
__device__ __forceinline__ ull ld_vol_smem_u64(unsigned addr) {
    ull v;
    asm volatile("ld.volatile.shared.b64 %0, [%1];" : "=l"(v) : "r"(addr));
    return v;
}
__device__ __forceinline__ void cluster_sync_all() {
    asm volatile("barrier.cluster.arrive.aligned;" ::: "memory");
    asm volatile("barrier.cluster.wait.aligned;" ::: "memory");
}

// ---- f32x2 packed math ----
__device__ __forceinline__ ull pack2(float lo, float hi) {
    ull r; asm("mov.b64 %0, {%1, %2};" : "=l"(r) : "f"(lo), "f"(hi)); return r;
}
__device__ __forceinline__ void unpack2(ull v, float& lo, float& hi) {
    asm("mov.b64 {%0, %1}, %2;" : "=f"(lo), "=f"(hi) : "l"(v));
}
__device__ __forceinline__ ull fma2(ull a, ull b, ull c) {
    ull d; asm("fma.rn.f32x2 %0, %1, %2, %3;" : "=l"(d) : "l"(a), "l"(b), "l"(c));
    return d;
}
// saturating scalar fma: clamps result to [0,1] as a free output modifier
__device__ __forceinline__ float fma_sat(float a, float b, float c) {
    float d; asm("fma.rn.sat.f32 %0, %1, %2, %3;" : "=f"(d) : "f"(a), "f"(b), "f"(c));
    return d;
}

// ---------------------------------------------------------------------------
__global__ void __launch_bounds__(kThreads, 1) __cluster_dims__(4, 1, 1)
plastic_kernel(const float* __restrict__ x,
               const float* __restrict__ Wi,
               const float* __restrict__ bi,
               const float* __restrict__ w,
               const float* __restrict__ alpha,
               const float* __restrict__ Wm,
               const float* __restrict__ bm,
               const float* __restrict__ Wf,
               const float* __restrict__ bf,
               float* __restrict__ out) {
    const int b = blockIdx.x >> 2;
    const int c = blockIdx.x & 3;      // cluster ctarank
    const int t = threadIdx.x;
    const int lane = t & 31;
    const int wid = t >> 5;
    const int i0 = c * kRows;

    __shared__ __align__(16) float hbuf[2][kH];       // h double buffer
    __shared__ __align__(16) ull slots[2][4][kH];     // (tag,value) msgs, dbl buf
    __shared__ __align__(16) float wpart[8];          // per-warp eta partials

    // ======== prologue: xwi for steps [16c, 16c+16) of sample b ========
    {
        float* xs = reinterpret_cast<float*>(slots);  // 8KB scratch alias
        const float bi_t = __ldg(&bi[t]);
        const int s0 = c * 16;
        if (t < kI) {
#pragma unroll
            for (int s = 0; s < 16; ++s)
                xs[s * kI + t] = __ldg(&x[((s0 + s) * kB + b) * kI + t]);
        }
        __syncthreads();
        float acc[16];
#pragma unroll
        for (int s = 0; s < 16; ++s) acc[s] = bi_t;
#pragma unroll 4
        for (int ib = 0; ib < kI; ib += 4) {
            const float q0 = __ldg(&Wi[(ib + 0) * kH + t]);
            const float q1 = __ldg(&Wi[(ib + 1) * kH + t]);
            const float q2 = __ldg(&Wi[(ib + 2) * kH + t]);
            const float q3 = __ldg(&Wi[(ib + 3) * kH + t]);
#pragma unroll
            for (int s = 0; s < 16; ++s) {
                const float4 xv = *reinterpret_cast<const float4*>(&xs[s * kI + ib]);
                acc[s] = fmaf(xv.w, q3, fmaf(xv.z, q2,
                         fmaf(xv.y, q1, fmaf(xv.x, q0, acc[s]))));
            }
        }
#pragma unroll
        for (int s = 0; s < 16; ++s)
            g_xwi[((s0 + s) * kB + b) * kH + t] = acc[s];
    }
    __syncthreads();   // xs scratch reads done before slot tag init below

    // ======== register state: rows i0+2j, i0+2j+1, column t ========
    // wv2 = (w - 2a) pair, av2 = (4a) pair, hbs = (hebb+2)/4 in [0,1]
    ull wv2[32], av2[32];
    float hbL[32], hbH[32];
#pragma unroll
    for (int j = 0; j < 32; ++j) {
        const float w0 = __ldg(&w[(i0 + 2 * j) * kH + t]);
        const float w1 = __ldg(&w[(i0 + 2 * j + 1) * kH + t]);
        const float a0 = __ldg(&alpha[(i0 + 2 * j) * kH + t]);
        const float a1 = __ldg(&alpha[(i0 + 2 * j + 1) * kH + t]);
        wv2[j] = pack2(fmaf(-2.f, a0, w0), fmaf(-2.f, a1, w1));
        av2[j] = pack2(4.f * a0, 4.f * a1);
        hbL[j] = 0.5f;   // hebb = 0
        hbH[j] = 0.5f;
    }
    const float wf_t = __ldg(&Wf[t]);
    const float bf_t = __ldg(&bf[t]);
    const float wm_t = __ldg(&Wm[t]);
    const float bm0 = __ldg(&bm[0]);

    // invalid tags everywhere (0xFFFFFFFF != any step)
#pragma unroll
    for (int p = 0; p < 2; ++p)
#pragma unroll
        for (int r = 0; r < 4; ++r)
            slots[p][r][t] = 0xFFFFFFFF00000000ull;
    hbuf[0][t] = 0.f;   // h_{-1} = 0
    __syncthreads();
    // one-time barrier: peers' smem live, g_xwi stores visible to __ldcg
    cluster_sync_all();

    // push / spin addresses as DISTINCT SCALARS (compile-time selected)
    const unsigned lr0 = smem_u32(&slots[0][c][t]);
    const unsigned lr1 = smem_u32(&slots[1][c][t]);
    const unsigned pa00 = mapa_u32(lr0, (unsigned)((c + 1) & 3));
    const unsigned pa01 = mapa_u32(lr0, (unsigned)((c + 2) & 3));
    const unsigned pa02 = mapa_u32(lr0, (unsigned)((c + 3) & 3));
    const unsigned pa10 = mapa_u32(lr1, (unsigned)((c + 1) & 3));
    const unsigned pa11 = mapa_u32(lr1, (unsigned)((c + 2) & 3));
    const unsigned pa12 = mapa_u32(lr1, (unsigned)((c + 3) & 3));
    const unsigned sl00 = smem_u32(&slots[0][(c + 1) & 3][t]);
    const unsigned sl01 = smem_u32(&slots[0][(c + 2) & 3][t]);
    const unsigned sl02 = smem_u32(&slots[0][(c + 3) & 3][t]);
    const unsigned sl10 = smem_u32(&slots[1][(c + 1) & 3][t]);
    const unsigned sl11 = smem_u32(&slots[1][(c + 2) & 3][t]);
    const unsigned sl12 = smem_u32(&slots[1][(c + 3) & 3][t]);

    float* __restrict__ ys = out;
    float* __restrict__ hf = out + kT * kB * kH;
    float* __restrict__ hebbf = out + kT * kB * kH + kB * kH;

    // step 0: h_{-1}=0 -> rec=0 -> h = tanh(xwi[0])  (coherent load)
    float h_cur = tanhf(__ldcg(&g_xwi[b * kH + t]));

// One recurrence step with compile-time parity. HP/HN are constant smem
// arrays; PRA*/SLA* are the parity's scalar addresses.
#define STEP_BODY(STEP, HP, HN, PRA0, PRA1, PRA2, SLA0, SLA1, SLA2)            \
    {                                                                          \
        const int step_ = (STEP);                                              \
        float xw_next = 0.f;                                                   \
        if (step_ < kT - 1)                                                    \
            xw_next = __ldcg(&g_xwi[((step_ + 1) * kB + b) * kH + t]);         \
        HN[t] = h_cur;                                                         \
        if (c == 0) ys[(step_ * kB + b) * kH + t] = h_cur;                     \
        float s_ = h_cur * wm_t;                                               \
        _Pragma("unroll")                                                      \
        for (int off = 16; off; off >>= 1)                                     \
            s_ += __shfl_xor_sync(0xffffffffu, s_, off);                       \
        if (lane == 0) wpart[wid] = s_;                                        \
        __syncthreads();                                                       \
        const float4 wp0 = *reinterpret_cast<const float4*>(&wpart[0]);        \
        const float4 wp1 = *reinterpret_cast<const float4*>(&wpart[4]);        \
        const float eta = tanhf(((wp0.x + wp0.y) + (wp0.z + wp0.w)) +          \
                                ((wp1.x + wp1.y) + (wp1.z + wp1.w)) + bm0);    \
        const float v = fmaf(eta, wf_t, bf_t) * h_cur;                         \
        const float v4 = 0.25f * v;                                            \
        ull prA = 0ull, prB = 0ull;                                            \
        _Pragma("unroll")                                                      \
        for (int jj = 0; jj < 16; ++jj) {                                      \
            const float4 hp4 =                                                 \
                *reinterpret_cast<const float4*>(&HP[i0 + 4 * jj]);            \
            const float4 hn4 =                                                 \
                *reinterpret_cast<const float4*>(&HN[i0 + 4 * jj]);            \
            const int j = 2 * jj;                                              \
            hbL[j]     = fma_sat(v4, hp4.x, hbL[j]);                           \
            hbH[j]     = fma_sat(v4, hp4.y, hbH[j]);                           \
            hbL[j + 1] = fma_sat(v4, hp4.z, hbL[j + 1]);                       \
            hbH[j + 1] = fma_sat(v4, hp4.w, hbH[j + 1]);                       \
            prA = fma2(pack2(hn4.x, hn4.y),                                    \
                       fma2(av2[j], pack2(hbL[j], hbH[j]), wv2[j]), prA);      \
            prB = fma2(pack2(hn4.z, hn4.w),                                    \
                       fma2(av2[j + 1], pack2(hbL[j + 1], hbH[j + 1]),         \
                            wv2[j + 1]), prB);                                 \
        }                                                                      \
        if (step_ < kT - 1) {                                                  \
            float pa_, pb_, pc_, pd_;                                          \
            unpack2(prA, pa_, pb_);                                            \
            unpack2(prB, pc_, pd_);                                            \
            const float pr = (pa_ + pb_) + (pc_ + pd_);                        \
            const ull msg = ((ull)(unsigned)step_ << 32) |                     \
                            (ull)(unsigned)__float_as_uint(pr);                \
            st_cluster_u64(PRA0, msg);                                         \
            st_cluster_u64(PRA1, msg);                                         \
            st_cluster_u64(PRA2, msg);                                         \
            const unsigned tag = (unsigned)step_;                              \
            ull v0 = ld_vol_smem_u64(SLA0);                                    \
            ull v1 = ld_vol_smem_u64(SLA1);                                    \
            ull v2 = ld_vol_smem_u64(SLA2);                                    \
            while ((unsigned)(v0 >> 32) != tag) v0 = ld_vol_smem_u64(SLA0);    \
            while ((unsigned)(v1 >> 32) != tag) v1 = ld_vol_smem_u64(SLA1);    \
            while ((unsigned)(v2 >> 32) != tag) v2 = ld_vol_smem_u64(SLA2);    \
            const float q0 = __uint_as_float((unsigned)v0);                    \
            const float q1 = __uint_as_float((unsigned)v1);                    \
            const float q2 = __uint_as_float((unsigned)v2);                    \
            __syncthreads();                                                   \
            h_cur = tanhf(xw_next + ((pr + q0) + (q1 + q2)));                  \
        }                                                                      \
    }

    for (int step2 = 0; step2 < kT; step2 += 2) {
        // parity 0: hp = hbuf[0], hn = hbuf[1]
        STEP_BODY(step2,     hbuf[0], hbuf[1], pa00, pa01, pa02, sl00, sl01, sl02)
        // parity 1: hp = hbuf[1], hn = hbuf[0]
        STEP_BODY(step2 + 1, hbuf[1], hbuf[0], pa10, pa11, pa12, sl10, sl11, sl12)
    }
#undef STEP_BODY

    // ---- final outputs (hebb = 4*hbs - 2) ----
    if (c == 0) hf[b * kH + t] = h_cur;    // h at step T-1
#pragma unroll
    for (int j = 0; j < 32; ++j) {
        hebbf[(size_t)b * kH * kH + (i0 + 2 * j) * kH + t] =
            fmaf(4.f, hbL[j], -2.f);
        hebbf[(size_t)b * kH * kH + (i0 + 2 * j + 1) * kH + t] =
            fmaf(4.f, hbH[j], -2.f);
    }
}

// ---------------------------------------------------------------------------
extern "C" void kernel_launch(void* const* d_in, const int* in_sizes, int n_in,
                              void* d_out, int out_size) {
    const float* x     = (const float*)d_in[0];
    const float* Wi    = (const float*)d_in[1];
    const float* bi    = (const float*)d_in[2];
    const float* w     = (const float*)d_in[3];
    const float* alpha = (const float*)d_in[4];
    const float* Wm    = (const float*)d_in[5];
    const float* bm    = (const float*)d_in[6];
    const float* Wf    = (const float*)d_in[7];
    const float* bf    = (const float*)d_in[8];
    float* out = (float*)d_out;

    plastic_kernel<<<kNCTA, kThreads>>>(x, Wi, bi, w, alpha, Wm, bm, Wf, bf, out);
}